// round 2
// baseline (speedup 1.0000x reference)
#include <cuda_runtime.h>
#include <math.h>

// Problem constants
#define Bc 2
#define Nn 2048
#define DIMc 1024
#define Hh 16
#define HDc 64
#define Pp 2
#define M_ROWS (Bc * Nn)        // 4096
#define THREE_DIM (3 * DIMc)    // 3072

// Scratch (no cudaMalloc allowed)
__device__ float g_qkv[M_ROWS * THREE_DIM];          // 50 MB
__device__ float g_q[Bc * Hh * Nn * HDc];            // 16 MB, layout (b,h,n,d)
__device__ float g_k[Bc * Hh * Nn * HDc];
__device__ float g_v[Bc * Hh * Nn * HDc];
__device__ float g_attn[M_ROWS * DIMc];              // layout (b*n, h*HD)

// ---------------------------------------------------------------------------
// Classic 128x128x8 SIMT fp32 GEMM, 8x8 micro-tiles, optional bias epilogue.
// C[M,N] = A[M,K] @ B[K,N] (+ bias[N])
// ---------------------------------------------------------------------------
__global__ __launch_bounds__(256) void sgemm128(
    const float* __restrict__ A, const float* __restrict__ B,
    float* __restrict__ C, int M, int N, int K,
    const float* __restrict__ bias)
{
    const int BM = 128, BN = 128, BK = 8, TM = 8, TN = 8;
    __shared__ float As[BK][BM];   // transposed A tile
    __shared__ float Bs[BK][BN];

    int tid = threadIdx.x;
    int tr = tid >> 4;       // 0..15
    int tc = tid & 15;       // 0..15
    int rowBlock = blockIdx.y * BM;
    int colBlock = blockIdx.x * BN;

    int arow = tid >> 1;          // 0..127
    int acol = (tid & 1) * 4;     // 0 or 4
    int brow = tid >> 5;          // 0..7
    int bcol = (tid & 31) * 4;    // 0..124

    float acc[TM][TN];
#pragma unroll
    for (int i = 0; i < TM; i++)
#pragma unroll
        for (int j = 0; j < TN; j++) acc[i][j] = 0.f;

    const float* Aptr = A + (size_t)(rowBlock + arow) * K + acol;
    const float* Bptr = B + (size_t)brow * N + colBlock + bcol;

    for (int k0 = 0; k0 < K; k0 += BK) {
        float4 a4 = *reinterpret_cast<const float4*>(Aptr);
        float4 b4 = *reinterpret_cast<const float4*>(Bptr);
        Aptr += BK;
        Bptr += (size_t)BK * N;

        As[acol + 0][arow] = a4.x;
        As[acol + 1][arow] = a4.y;
        As[acol + 2][arow] = a4.z;
        As[acol + 3][arow] = a4.w;
        *reinterpret_cast<float4*>(&Bs[brow][bcol]) = b4;
        __syncthreads();

#pragma unroll
        for (int kk = 0; kk < BK; kk++) {
            float regM[TM], regN[TN];
            *reinterpret_cast<float4*>(&regM[0]) = *reinterpret_cast<const float4*>(&As[kk][tr * TM]);
            *reinterpret_cast<float4*>(&regM[4]) = *reinterpret_cast<const float4*>(&As[kk][tr * TM + 4]);
            *reinterpret_cast<float4*>(&regN[0]) = *reinterpret_cast<const float4*>(&Bs[kk][tc * TN]);
            *reinterpret_cast<float4*>(&regN[4]) = *reinterpret_cast<const float4*>(&Bs[kk][tc * TN + 4]);
#pragma unroll
            for (int i = 0; i < TM; i++)
#pragma unroll
                for (int j = 0; j < TN; j++)
                    acc[i][j] += regM[i] * regN[j];
        }
        __syncthreads();
    }

#pragma unroll
    for (int i = 0; i < TM; i++) {
        int row = rowBlock + tr * TM + i;
#pragma unroll
        for (int j = 0; j < TN; j += 4) {
            int col = colBlock + tc * TN + j;
            float4 o;
            o.x = acc[i][j + 0];
            o.y = acc[i][j + 1];
            o.z = acc[i][j + 2];
            o.w = acc[i][j + 3];
            if (bias) {
                o.x += bias[col + 0];
                o.y += bias[col + 1];
                o.z += bias[col + 2];
                o.w += bias[col + 3];
            }
            *reinterpret_cast<float4*>(&C[(size_t)row * N + col]) = o;
        }
    }
}

// ---------------------------------------------------------------------------
// Axial RoPE on q,k + scatter q,k,v from (b,n, 3*DIM) into (b,h,n,d) layout.
// Grid-stride over (b,n) pairs; 256 threads handle 16 heads x 32 pairs each.
// ---------------------------------------------------------------------------
__global__ __launch_bounds__(256) void rope_scatter(
    const float* __restrict__ qkv, const float* __restrict__ pos,
    float* __restrict__ qo, float* __restrict__ ko, float* __restrict__ vo)
{
    int t = threadIdx.x;
    for (int bn = blockIdx.x; bn < M_ROWS; bn += gridDim.x) {
        int b = bn / Nn, n = bn % Nn;
        __shared__ float cs[32], sn[32];
        if (t < 32) {
            int p = t >> 4, i = t & 15;
            // freq = 10000^(-i/16) = exp(-i * ln(10000)/16)
            float freq = expf(-(float)i * (9.210340371976184f / 16.f));
            float th = pos[(size_t)bn * Pp + p] * freq;
            float s, c;
            sincosf(th, &s, &c);
            cs[t] = c;
            sn[t] = s;
        }
        __syncthreads();
        const float* base = qkv + (size_t)bn * THREE_DIM;
        for (int idx = t; idx < Hh * 32; idx += 256) {
            int h = idx >> 5, d = idx & 31;
            float c = cs[d], s = sn[d];
            size_t off = ((size_t)(b * Hh + h) * Nn + n) * HDc;
            // q
            float x1 = base[h * HDc + d];
            float x2 = base[h * HDc + 32 + d];
            qo[off + d]      = x1 * c - x2 * s;
            qo[off + 32 + d] = x1 * s + x2 * c;
            // k
            x1 = base[DIMc + h * HDc + d];
            x2 = base[DIMc + h * HDc + 32 + d];
            ko[off + d]      = x1 * c - x2 * s;
            ko[off + 32 + d] = x1 * s + x2 * c;
            // v passthrough
            vo[off + d]      = base[2 * DIMc + h * HDc + d];
            vo[off + 32 + d] = base[2 * DIMc + h * HDc + 32 + d];
        }
        __syncthreads();
    }
}

// ---------------------------------------------------------------------------
// Flash attention, fp32 SIMT. 64-query tile per block, 64-key tiles, online
// softmax. Output written directly in (b*n, h*HD) layout for the out-proj GEMM.
// ---------------------------------------------------------------------------
#define FLASH_LD 65
#define FLASH_SMEM_FLOATS (4 * 64 * FLASH_LD + 3 * 64 + 256)
#define FLASH_SMEM_BYTES (FLASH_SMEM_FLOATS * 4)

__global__ __launch_bounds__(256) void flash_kernel(
    const float* __restrict__ Q, const float* __restrict__ K,
    const float* __restrict__ V, float* __restrict__ O)
{
    extern __shared__ float sm[];
    float* Qs = sm;                       // 64 x FLASH_LD
    float* Ks = Qs + 64 * FLASH_LD;
    float* Vs = Ks + 64 * FLASH_LD;
    float* Ss = Vs + 64 * FLASH_LD;
    float* mrow = Ss + 64 * FLASH_LD;     // 64
    float* lrow = mrow + 64;              // 64
    float* crow = lrow + 64;              // 64
    float* red  = crow + 64;              // 64*4

    int tid = threadIdx.x;
    int qt = blockIdx.x;        // query tile
    int bh = blockIdx.y;        // b*H + h
    const float* Qb = Q + ((size_t)bh * Nn + qt * 64) * HDc;
    const float* Kb = K + (size_t)bh * Nn * HDc;
    const float* Vb = V + (size_t)bh * Nn * HDc;

    // load Q tile (64x64) once
    for (int i = tid; i < 64 * 16; i += 256) {
        int r = i >> 4, c4 = (i & 15) * 4;
        float4 v4 = *reinterpret_cast<const float4*>(Qb + (size_t)r * HDc + c4);
        Qs[r * FLASH_LD + c4 + 0] = v4.x;
        Qs[r * FLASH_LD + c4 + 1] = v4.y;
        Qs[r * FLASH_LD + c4 + 2] = v4.z;
        Qs[r * FLASH_LD + c4 + 3] = v4.w;
    }
    if (tid < 64) { mrow[tid] = -INFINITY; lrow[tid] = 0.f; }

    int tr = tid >> 4, tc = tid & 15;     // 16x16 thread grid, 4x4 micro-tiles
    int rr = tid >> 2, rq = tid & 3;      // row / quarter for reductions
    float acc[4][4] = {};
    const float scale = 0.125f;           // 1/sqrt(64)

    for (int kt = 0; kt < Nn / 64; kt++) {
        __syncthreads();   // prev tile fully consumed (also covers Q/m/l init)
        // load K,V tiles
        for (int i = tid; i < 64 * 16; i += 256) {
            int r = i >> 4, c4 = (i & 15) * 4;
            const float* kp = Kb + ((size_t)(kt * 64 + r)) * HDc + c4;
            const float* vp = Vb + ((size_t)(kt * 64 + r)) * HDc + c4;
            float4 k4 = *reinterpret_cast<const float4*>(kp);
            float4 v4 = *reinterpret_cast<const float4*>(vp);
            Ks[r * FLASH_LD + c4 + 0] = k4.x;
            Ks[r * FLASH_LD + c4 + 1] = k4.y;
            Ks[r * FLASH_LD + c4 + 2] = k4.z;
            Ks[r * FLASH_LD + c4 + 3] = k4.w;
            Vs[r * FLASH_LD + c4 + 0] = v4.x;
            Vs[r * FLASH_LD + c4 + 1] = v4.y;
            Vs[r * FLASH_LD + c4 + 2] = v4.z;
            Vs[r * FLASH_LD + c4 + 3] = v4.w;
        }
        __syncthreads();

        // S = scale * Q @ K^T (4x4 micro-tile per thread)
        float s4[4][4] = {};
#pragma unroll 8
        for (int kk = 0; kk < HDc; kk++) {
            float qv[4], kv[4];
#pragma unroll
            for (int i = 0; i < 4; i++) qv[i] = Qs[(tr * 4 + i) * FLASH_LD + kk];
#pragma unroll
            for (int j = 0; j < 4; j++) kv[j] = Ks[(tc * 4 + j) * FLASH_LD + kk];
#pragma unroll
            for (int i = 0; i < 4; i++)
#pragma unroll
                for (int j = 0; j < 4; j++)
                    s4[i][j] += qv[i] * kv[j];
        }
#pragma unroll
        for (int i = 0; i < 4; i++)
#pragma unroll
            for (int j = 0; j < 4; j++)
                Ss[(tr * 4 + i) * FLASH_LD + tc * 4 + j] = s4[i][j] * scale;
        __syncthreads();

        // row max (4 threads per row)
        float pm = -INFINITY;
#pragma unroll
        for (int j = 0; j < 16; j++) pm = fmaxf(pm, Ss[rr * FLASH_LD + rq * 16 + j]);
        red[rr * 4 + rq] = pm;
        __syncthreads();
        if (rq == 0) {
            float m_old = mrow[rr];
            float tm = fmaxf(fmaxf(red[rr * 4], red[rr * 4 + 1]),
                             fmaxf(red[rr * 4 + 2], red[rr * 4 + 3]));
            float m_new = fmaxf(m_old, tm);
            mrow[rr] = m_new;
            crow[rr] = expf(m_old - m_new);   // 0 on first tile
        }
        __syncthreads();

        // exponentiate + partial row sums
        float m_new = mrow[rr];
        float ps = 0.f;
#pragma unroll
        for (int j = 0; j < 16; j++) {
            float e = expf(Ss[rr * FLASH_LD + rq * 16 + j] - m_new);
            Ss[rr * FLASH_LD + rq * 16 + j] = e;
            ps += e;
        }
        red[rr * 4 + rq] = ps;
        __syncthreads();
        if (rq == 0)
            lrow[rr] = lrow[rr] * crow[rr] +
                       red[rr * 4] + red[rr * 4 + 1] + red[rr * 4 + 2] + red[rr * 4 + 3];

        // rescale accumulator, then O += P @ V
        float cr[4];
#pragma unroll
        for (int i = 0; i < 4; i++) cr[i] = crow[tr * 4 + i];
#pragma unroll
        for (int i = 0; i < 4; i++)
#pragma unroll
            for (int j = 0; j < 4; j++) acc[i][j] *= cr[i];

#pragma unroll 8
        for (int kk = 0; kk < 64; kk++) {
            float pv[4], vv[4];
#pragma unroll
            for (int i = 0; i < 4; i++) pv[i] = Ss[(tr * 4 + i) * FLASH_LD + kk];
#pragma unroll
            for (int j = 0; j < 4; j++) vv[j] = Vs[kk * FLASH_LD + tc * 4 + j];
#pragma unroll
            for (int i = 0; i < 4; i++)
#pragma unroll
                for (int j = 0; j < 4; j++)
                    acc[i][j] += pv[i] * vv[j];
        }
    }
    __syncthreads();

    // normalize + store to (b*n, h*HD) layout
    int b = bh / Hh, h = bh % Hh;
    float inv[4];
#pragma unroll
    for (int i = 0; i < 4; i++) inv[i] = 1.f / lrow[tr * 4 + i];
#pragma unroll
    for (int i = 0; i < 4; i++) {
        int nglob = qt * 64 + tr * 4 + i;
        size_t rowoff = ((size_t)b * Nn + nglob) * DIMc + h * HDc + tc * 4;
#pragma unroll
        for (int j = 0; j < 4; j++)
            O[rowoff + j] = acc[i][j] * inv[i];
    }
}

// ---------------------------------------------------------------------------
extern "C" void kernel_launch(void* const* d_in, const int* in_sizes, int n_in,
                              void* d_out, int out_size)
{
    (void)in_sizes; (void)n_in; (void)out_size;
    const float* x     = (const float*)d_in[0];
    const float* pos   = (const float*)d_in[1];
    const float* w_qkv = (const float*)d_in[2];
    const float* w_out = (const float*)d_in[3];
    const float* b_out = (const float*)d_in[4];
    float* out = (float*)d_out;

    float *qkv, *q, *k, *v, *attn;
    cudaGetSymbolAddress((void**)&qkv,  g_qkv);
    cudaGetSymbolAddress((void**)&q,    g_q);
    cudaGetSymbolAddress((void**)&k,    g_k);
    cudaGetSymbolAddress((void**)&v,    g_v);
    cudaGetSymbolAddress((void**)&attn, g_attn);

    cudaFuncSetAttribute(flash_kernel,
                         cudaFuncAttributeMaxDynamicSharedMemorySize,
                         FLASH_SMEM_BYTES);

    // 1) QKV projection
    {
        dim3 grid(THREE_DIM / 128, M_ROWS / 128);
        sgemm128<<<grid, 256>>>(x, w_qkv, qkv, M_ROWS, THREE_DIM, DIMc, nullptr);
    }
    // 2) RoPE + scatter to (b,h,n,d)
    rope_scatter<<<512, 256>>>(qkv, pos, q, k, v);
    // 3) Flash attention -> (b*n, h*HD)
    {
        dim3 grid(Nn / 64, Bc * Hh);
        flash_kernel<<<grid, 256, FLASH_SMEM_BYTES>>>(q, k, v, attn);
    }
    // 4) Output projection + bias
    {
        dim3 grid(DIMc / 128, M_ROWS / 128);
        sgemm128<<<grid, 256>>>(attn, w_out, out, M_ROWS, DIMc, DIMc, b_out);
    }
}

// round 4
// speedup vs baseline: 3.1802x; 3.1802x over previous
#include <cuda_runtime.h>
#include <math.h>
#include <stdint.h>

// Problem constants
#define Bc 2
#define Nn 2048
#define DIMc 1024
#define Hh 16
#define HDc 64
#define Pp 2
#define M_ROWS (Bc * Nn)        // 4096
#define THREE_DIM (3 * DIMc)    // 3072

// Scratch (no cudaMalloc allowed)
__device__ float g_qkv[M_ROWS * THREE_DIM];
__device__ float g_q[Bc * Hh * Nn * HDc];   // (b,h,n,d)
__device__ float g_k[Bc * Hh * Nn * HDc];
__device__ float g_v[Bc * Hh * Nn * HDc];
__device__ float g_attn[M_ROWS * DIMc];     // (b*n, h*HD)

// ---------------------------------------------------------------------------
// helpers
// ---------------------------------------------------------------------------
__device__ __forceinline__ uint32_t f2tf(float x) {
    uint32_t r;
    asm("cvt.rna.tf32.f32 %0, %1;" : "=r"(r) : "f"(x));
    return r;
}
__device__ __forceinline__ float ex2(float x) {
    float r;
    asm("ex2.approx.ftz.f32 %0, %1;" : "=f"(r) : "f"(x));
    return r;
}
__device__ __forceinline__ void mma_tf32(float d[4], const uint32_t a[4], const uint32_t b[2]) {
    asm volatile(
        "mma.sync.aligned.m16n8k8.row.col.f32.tf32.tf32.f32 "
        "{%0,%1,%2,%3}, {%4,%5,%6,%7}, {%8,%9}, {%0,%1,%2,%3};\n"
        : "+f"(d[0]), "+f"(d[1]), "+f"(d[2]), "+f"(d[3])
        : "r"(a[0]), "r"(a[1]), "r"(a[2]), "r"(a[3]), "r"(b[0]), "r"(b[1]));
}

// ---------------------------------------------------------------------------
// tf32 tensor-core GEMM: C[M,N] = A[M,K] @ B[K,N] (+bias). M,N mult of 128,
// K mult of 16. 128 threads = 4 warps (2x2), warp tile 64x64.
// ---------------------------------------------------------------------------
#define GAP 20    // As pitch (floats)
#define GBP 136   // Bs pitch (floats)

__global__ __launch_bounds__(128) void gemm_tf32(
    const float* __restrict__ A, const float* __restrict__ B,
    float* __restrict__ C, int M, int N, int K,
    const float* __restrict__ bias)
{
    __shared__ float As[2][128 * GAP];
    __shared__ float Bs[2][16 * GBP];

    int tid = threadIdx.x, lane = tid & 31, warp = tid >> 5;
    int wm = (warp >> 1) * 64, wn = (warp & 1) * 64;
    int rb = blockIdx.y * 128, cb = blockIdx.x * 128;

    int ar = tid >> 2, ac = (tid & 3) * 4;    // A rows ar+32p, cols ac..ac+3
    int bk = tid >> 5, bn = (tid & 31) * 4;   // B rows bk+4p,  cols bn..bn+3

    float4 arg[4], brg[4];
    float acc[4][8][4];
#pragma unroll
    for (int mt = 0; mt < 4; mt++)
#pragma unroll
        for (int nt = 0; nt < 8; nt++)
#pragma unroll
            for (int i = 0; i < 4; i++) acc[mt][nt][i] = 0.f;

    // prologue load tile 0
#pragma unroll
    for (int p = 0; p < 4; p++)
        arg[p] = *(const float4*)&A[(size_t)(rb + ar + 32 * p) * K + ac];
#pragma unroll
    for (int p = 0; p < 4; p++)
        brg[p] = *(const float4*)&B[(size_t)(bk + 4 * p) * N + cb + bn];
    // store tile 0 (convert to tf32 bit patterns)
#pragma unroll
    for (int p = 0; p < 4; p++) {
        float4 t;
        t.x = __uint_as_float(f2tf(arg[p].x));
        t.y = __uint_as_float(f2tf(arg[p].y));
        t.z = __uint_as_float(f2tf(arg[p].z));
        t.w = __uint_as_float(f2tf(arg[p].w));
        *(float4*)&As[0][(ar + 32 * p) * GAP + ac] = t;
    }
#pragma unroll
    for (int p = 0; p < 4; p++) {
        float4 t;
        t.x = __uint_as_float(f2tf(brg[p].x));
        t.y = __uint_as_float(f2tf(brg[p].y));
        t.z = __uint_as_float(f2tf(brg[p].z));
        t.w = __uint_as_float(f2tf(brg[p].w));
        *(float4*)&Bs[0][(bk + 4 * p) * GBP + bn] = t;
    }
    __syncthreads();

    int nk = K / 16;
    for (int kb2 = 0; kb2 < nk; kb2++) {
        if (kb2 + 1 < nk) {
            int k0 = (kb2 + 1) * 16;
#pragma unroll
            for (int p = 0; p < 4; p++)
                arg[p] = *(const float4*)&A[(size_t)(rb + ar + 32 * p) * K + k0 + ac];
#pragma unroll
            for (int p = 0; p < 4; p++)
                brg[p] = *(const float4*)&B[(size_t)(k0 + bk + 4 * p) * N + cb + bn];
        }
        int s = kb2 & 1;
#pragma unroll
        for (int ks = 0; ks < 2; ks++) {
            int kb = ks * 8 + (lane & 3);
            uint32_t afr[4][4], bfr[8][2];
#pragma unroll
            for (int mt = 0; mt < 4; mt++) {
                int r0 = wm + mt * 16 + (lane >> 2);
                afr[mt][0] = __float_as_uint(As[s][r0 * GAP + kb]);
                afr[mt][1] = __float_as_uint(As[s][(r0 + 8) * GAP + kb]);
                afr[mt][2] = __float_as_uint(As[s][r0 * GAP + kb + 4]);
                afr[mt][3] = __float_as_uint(As[s][(r0 + 8) * GAP + kb + 4]);
            }
#pragma unroll
            for (int nt = 0; nt < 8; nt++) {
                int n0 = wn + nt * 8 + (lane >> 2);
                bfr[nt][0] = __float_as_uint(Bs[s][kb * GBP + n0]);
                bfr[nt][1] = __float_as_uint(Bs[s][(kb + 4) * GBP + n0]);
            }
#pragma unroll
            for (int mt = 0; mt < 4; mt++)
#pragma unroll
                for (int nt = 0; nt < 8; nt++)
                    mma_tf32(acc[mt][nt], afr[mt], bfr[nt]);
        }
        __syncthreads();
        if (kb2 + 1 < nk) {
            int s2 = (kb2 + 1) & 1;
#pragma unroll
            for (int p = 0; p < 4; p++) {
                float4 t;
                t.x = __uint_as_float(f2tf(arg[p].x));
                t.y = __uint_as_float(f2tf(arg[p].y));
                t.z = __uint_as_float(f2tf(arg[p].z));
                t.w = __uint_as_float(f2tf(arg[p].w));
                *(float4*)&As[s2][(ar + 32 * p) * GAP + ac] = t;
            }
#pragma unroll
            for (int p = 0; p < 4; p++) {
                float4 t;
                t.x = __uint_as_float(f2tf(brg[p].x));
                t.y = __uint_as_float(f2tf(brg[p].y));
                t.z = __uint_as_float(f2tf(brg[p].z));
                t.w = __uint_as_float(f2tf(brg[p].w));
                *(float4*)&Bs[s2][(bk + 4 * p) * GBP + bn] = t;
            }
            __syncthreads();
        }
    }

    // epilogue
#pragma unroll
    for (int mt = 0; mt < 4; mt++) {
        int r0 = rb + wm + mt * 16 + (lane >> 2);
#pragma unroll
        for (int nt = 0; nt < 8; nt++) {
            int c0 = cb + wn + nt * 8 + 2 * (lane & 3);
            float bx = 0.f, by = 0.f;
            if (bias) { bx = bias[c0]; by = bias[c0 + 1]; }
            float2 o0 = make_float2(acc[mt][nt][0] + bx, acc[mt][nt][1] + by);
            float2 o1 = make_float2(acc[mt][nt][2] + bx, acc[mt][nt][3] + by);
            *(float2*)&C[(size_t)r0 * N + c0] = o0;
            *(float2*)&C[(size_t)(r0 + 8) * N + c0] = o1;
        }
    }
}

// ---------------------------------------------------------------------------
// Axial RoPE + scatter to (b,h,n,d)
// ---------------------------------------------------------------------------
__global__ __launch_bounds__(256) void rope_scatter(
    const float* __restrict__ qkv, const float* __restrict__ pos,
    float* __restrict__ qo, float* __restrict__ ko, float* __restrict__ vo)
{
    int t = threadIdx.x;
    for (int bn = blockIdx.x; bn < M_ROWS; bn += gridDim.x) {
        int b = bn / Nn, n = bn % Nn;
        __shared__ float cs[32], sn[32];
        if (t < 32) {
            int p = t >> 4, i = t & 15;
            float freq = expf(-(float)i * (9.210340371976184f / 16.f));
            float th = pos[(size_t)bn * Pp + p] * freq;
            float s, c;
            sincosf(th, &s, &c);
            cs[t] = c;
            sn[t] = s;
        }
        __syncthreads();
        const float* base = qkv + (size_t)bn * THREE_DIM;
        for (int idx = t; idx < Hh * 32; idx += 256) {
            int h = idx >> 5, d = idx & 31;
            float c = cs[d], s = sn[d];
            size_t off = ((size_t)(b * Hh + h) * Nn + n) * HDc;
            float x1 = base[h * HDc + d];
            float x2 = base[h * HDc + 32 + d];
            qo[off + d]      = x1 * c - x2 * s;
            qo[off + 32 + d] = x1 * s + x2 * c;
            x1 = base[DIMc + h * HDc + d];
            x2 = base[DIMc + h * HDc + 32 + d];
            ko[off + d]      = x1 * c - x2 * s;
            ko[off + 32 + d] = x1 * s + x2 * c;
            vo[off + d]      = base[2 * DIMc + h * HDc + d];
            vo[off + 32 + d] = base[2 * DIMc + h * HDc + 32 + d];
        }
        __syncthreads();
    }
}

// ---------------------------------------------------------------------------
// Flash attention with tf32 mma. 128 threads = 4 warps in 2x2 over a
// 64(query) x 64(key) tile. Online softmax in exp2 domain (scale folded
// into Q). P staged through smem as tf32 for the PV mma.
// ---------------------------------------------------------------------------
#define FP 68
#define FLASH_SMEM_FLOATS (4 * 64 * FP + 64 + 64 + 128 + 128)
#define FLASH_SMEM_BYTES (FLASH_SMEM_FLOATS * 4)

__global__ __launch_bounds__(128) void flash_tf32(
    const float* __restrict__ Q, const float* __restrict__ K,
    const float* __restrict__ V, float* __restrict__ O)
{
    extern __shared__ float smf[];
    float* Qs = smf;
    float* Ks = Qs + 64 * FP;
    float* Vs = Ks + 64 * FP;
    float* Ps = Vs + 64 * FP;
    float* mrow = Ps + 64 * FP;   // 64
    float* lrow = mrow + 64;      // 64
    float* rmax = lrow + 64;      // 2*64
    float* rsum = rmax + 128;     // 2*64

    int tid = threadIdx.x, lane = tid & 31, warp = tid >> 5;
    int wm = (warp >> 1) * 32, wn = (warp & 1) * 32;
    int bh = blockIdx.y;
    int b = bh >> 4, h = bh & 15;
    int qt = blockIdx.x;

    const float* Qb = Q + ((size_t)bh * Nn + qt * 64) * HDc;
    const float* Kb = K + (size_t)bh * Nn * HDc;
    const float* Vb = V + (size_t)bh * Nn * HDc;

    const float SC = 0.125f * 1.44269504f;  // 1/sqrt(64) * log2(e)

    // load Q tile scaled+converted
    {
        int r = tid >> 4, c = (tid & 15) * 4;
#pragma unroll
        for (int p = 0; p < 8; p++) {
            int rr = r + 8 * p;
            float4 q4 = *(const float4*)&Qb[(size_t)rr * HDc + c];
            float4 t;
            t.x = __uint_as_float(f2tf(q4.x * SC));
            t.y = __uint_as_float(f2tf(q4.y * SC));
            t.z = __uint_as_float(f2tf(q4.z * SC));
            t.w = __uint_as_float(f2tf(q4.w * SC));
            *(float4*)&Qs[rr * FP + c] = t;
        }
    }
    if (tid < 64) { mrow[tid] = -1e30f; lrow[tid] = 0.f; }

    float accO[2][4][4];
#pragma unroll
    for (int mt = 0; mt < 2; mt++)
#pragma unroll
        for (int nt = 0; nt < 4; nt++)
#pragma unroll
            for (int i = 0; i < 4; i++) accO[mt][nt][i] = 0.f;

    __syncthreads();

    for (int kt = 0; kt < Nn / 64; kt++) {
        // load K,V tiles (converted to tf32)
        {
            int r = tid >> 4, c = (tid & 15) * 4;
#pragma unroll
            for (int p = 0; p < 8; p++) {
                int rr = r + 8 * p;
                float4 k4 = *(const float4*)&Kb[((size_t)(kt * 64 + rr)) * HDc + c];
                float4 v4 = *(const float4*)&Vb[((size_t)(kt * 64 + rr)) * HDc + c];
                float4 tk, tv;
                tk.x = __uint_as_float(f2tf(k4.x));
                tk.y = __uint_as_float(f2tf(k4.y));
                tk.z = __uint_as_float(f2tf(k4.z));
                tk.w = __uint_as_float(f2tf(k4.w));
                tv.x = __uint_as_float(f2tf(v4.x));
                tv.y = __uint_as_float(f2tf(v4.y));
                tv.z = __uint_as_float(f2tf(v4.z));
                tv.w = __uint_as_float(f2tf(v4.w));
                *(float4*)&Ks[rr * FP + c] = tk;
                *(float4*)&Vs[rr * FP + c] = tv;
            }
        }
        __syncthreads();   // (1) tiles ready

        // S = Qs @ Ks^T (warp tile 32x32)
        float s[2][4][4];
#pragma unroll
        for (int mt = 0; mt < 2; mt++)
#pragma unroll
            for (int nt = 0; nt < 4; nt++)
#pragma unroll
                for (int i = 0; i < 4; i++) s[mt][nt][i] = 0.f;
#pragma unroll
        for (int ks = 0; ks < 8; ks++) {
            int kb = ks * 8 + (lane & 3);
            uint32_t afr[2][4], bfr[4][2];
#pragma unroll
            for (int mt = 0; mt < 2; mt++) {
                int r0 = wm + mt * 16 + (lane >> 2);
                afr[mt][0] = __float_as_uint(Qs[r0 * FP + kb]);
                afr[mt][1] = __float_as_uint(Qs[(r0 + 8) * FP + kb]);
                afr[mt][2] = __float_as_uint(Qs[r0 * FP + kb + 4]);
                afr[mt][3] = __float_as_uint(Qs[(r0 + 8) * FP + kb + 4]);
            }
#pragma unroll
            for (int nt = 0; nt < 4; nt++) {
                int n0 = wn + nt * 8 + (lane >> 2);
                bfr[nt][0] = __float_as_uint(Ks[n0 * FP + kb]);
                bfr[nt][1] = __float_as_uint(Ks[n0 * FP + kb + 4]);
            }
#pragma unroll
            for (int mt = 0; mt < 2; mt++)
#pragma unroll
                for (int nt = 0; nt < 4; nt++)
                    mma_tf32(s[mt][nt], afr[mt], bfr[nt]);
        }

        // row max (per-thread -> bfly over lane%4 group -> smem)
        float mxa[2], mxb[2];
#pragma unroll
        for (int mt = 0; mt < 2; mt++) {
            float ma = -1e30f, mb = -1e30f;
#pragma unroll
            for (int nt = 0; nt < 4; nt++) {
                ma = fmaxf(ma, fmaxf(s[mt][nt][0], s[mt][nt][1]));
                mb = fmaxf(mb, fmaxf(s[mt][nt][2], s[mt][nt][3]));
            }
            ma = fmaxf(ma, __shfl_xor_sync(0xffffffffu, ma, 1));
            ma = fmaxf(ma, __shfl_xor_sync(0xffffffffu, ma, 2));
            mb = fmaxf(mb, __shfl_xor_sync(0xffffffffu, mb, 1));
            mb = fmaxf(mb, __shfl_xor_sync(0xffffffffu, mb, 2));
            mxa[mt] = ma; mxb[mt] = mb;
        }
        if ((lane & 3) == 0) {
#pragma unroll
            for (int mt = 0; mt < 2; mt++) {
                int rA = wm + mt * 16 + (lane >> 2);
                rmax[(warp & 1) * 64 + rA] = mxa[mt];
                rmax[(warp & 1) * 64 + rA + 8] = mxb[mt];
            }
        }
        __syncthreads();   // (2) rmax ready

        // m_new, rescale O, exponentiate, partial sums, store P
#pragma unroll
        for (int mt = 0; mt < 2; mt++) {
            int rA = wm + mt * 16 + (lane >> 2);
            int rB = rA + 8;
            float moA = mrow[rA];
            float moB = mrow[rB];
            float mnA = fmaxf(moA, fmaxf(rmax[rA], rmax[64 + rA]));
            float mnB = fmaxf(moB, fmaxf(rmax[rB], rmax[64 + rB]));
            float fA = ex2(moA - mnA);
            float fB = ex2(moB - mnB);
            float sa = 0.f, sb = 0.f;
#pragma unroll
            for (int nt = 0; nt < 4; nt++) {
                float p0 = ex2(s[mt][nt][0] - mnA);
                float p1 = ex2(s[mt][nt][1] - mnA);
                float p2 = ex2(s[mt][nt][2] - mnB);
                float p3 = ex2(s[mt][nt][3] - mnB);
                sa += p0 + p1;
                sb += p2 + p3;
                accO[mt][nt][0] *= fA;
                accO[mt][nt][1] *= fA;
                accO[mt][nt][2] *= fB;
                accO[mt][nt][3] *= fB;
                int base = rA * FP + wn + nt * 8 + 2 * (lane & 3);
                Ps[base]     = __uint_as_float(f2tf(p0));
                Ps[base + 1] = __uint_as_float(f2tf(p1));
                Ps[rB * FP + wn + nt * 8 + 2 * (lane & 3)]     = __uint_as_float(f2tf(p2));
                Ps[rB * FP + wn + nt * 8 + 2 * (lane & 3) + 1] = __uint_as_float(f2tf(p3));
            }
            sa += __shfl_xor_sync(0xffffffffu, sa, 1);
            sa += __shfl_xor_sync(0xffffffffu, sa, 2);
            sb += __shfl_xor_sync(0xffffffffu, sb, 1);
            sb += __shfl_xor_sync(0xffffffffu, sb, 2);
            if ((lane & 3) == 0) {
                rsum[(warp & 1) * 64 + rA] = sa;
                rsum[(warp & 1) * 64 + rB] = sb;
            }
        }
        __syncthreads();   // (3) P + rsum ready

        // update running stats (one thread per row)
        if (tid < 64) {
            int r = tid;
            float mo = mrow[r];
            float mn = fmaxf(mo, fmaxf(rmax[r], rmax[64 + r]));
            lrow[r] = lrow[r] * ex2(mo - mn) + rsum[r] + rsum[64 + r];
            mrow[r] = mn;
        }

        // O += P @ V
#pragma unroll
        for (int ks = 0; ks < 8; ks++) {
            int kb = ks * 8 + (lane & 3);
            uint32_t afr[2][4], bfr[4][2];
#pragma unroll
            for (int mt = 0; mt < 2; mt++) {
                int r0 = wm + mt * 16 + (lane >> 2);
                afr[mt][0] = __float_as_uint(Ps[r0 * FP + kb]);
                afr[mt][1] = __float_as_uint(Ps[(r0 + 8) * FP + kb]);
                afr[mt][2] = __float_as_uint(Ps[r0 * FP + kb + 4]);
                afr[mt][3] = __float_as_uint(Ps[(r0 + 8) * FP + kb + 4]);
            }
#pragma unroll
            for (int nt = 0; nt < 4; nt++) {
                int n0 = wn + nt * 8 + (lane >> 2);
                bfr[nt][0] = __float_as_uint(Vs[kb * FP + n0]);
                bfr[nt][1] = __float_as_uint(Vs[(kb + 4) * FP + n0]);
            }
#pragma unroll
            for (int mt = 0; mt < 2; mt++)
#pragma unroll
                for (int nt = 0; nt < 4; nt++)
                    mma_tf32(accO[mt][nt], afr[mt], bfr[nt]);
        }
        __syncthreads();   // (4) safe to overwrite tiles / stats visible
    }

    // epilogue: normalize and store to (b*n, h*HD)
#pragma unroll
    for (int mt = 0; mt < 2; mt++) {
        int rA = wm + mt * 16 + (lane >> 2);
        int rB = rA + 8;
        float ia = 1.f / lrow[rA];
        float ib = 1.f / lrow[rB];
        size_t rowA = ((size_t)(b * Nn + qt * 64 + rA)) * DIMc + h * HDc;
        size_t rowB = ((size_t)(b * Nn + qt * 64 + rB)) * DIMc + h * HDc;
#pragma unroll
        for (int nt = 0; nt < 4; nt++) {
            int c0 = wn + nt * 8 + 2 * (lane & 3);
            float2 oA = make_float2(accO[mt][nt][0] * ia, accO[mt][nt][1] * ia);
            float2 oB = make_float2(accO[mt][nt][2] * ib, accO[mt][nt][3] * ib);
            *(float2*)&O[rowA + c0] = oA;
            *(float2*)&O[rowB + c0] = oB;
        }
    }
}

// ---------------------------------------------------------------------------
extern "C" void kernel_launch(void* const* d_in, const int* in_sizes, int n_in,
                              void* d_out, int out_size)
{
    (void)in_sizes; (void)n_in; (void)out_size;
    const float* x     = (const float*)d_in[0];
    const float* pos   = (const float*)d_in[1];
    const float* w_qkv = (const float*)d_in[2];
    const float* w_out = (const float*)d_in[3];
    const float* b_out = (const float*)d_in[4];
    float* out = (float*)d_out;

    float *qkv, *q, *k, *v, *attn;
    cudaGetSymbolAddress((void**)&qkv,  g_qkv);
    cudaGetSymbolAddress((void**)&q,    g_q);
    cudaGetSymbolAddress((void**)&k,    g_k);
    cudaGetSymbolAddress((void**)&v,    g_v);
    cudaGetSymbolAddress((void**)&attn, g_attn);

    cudaFuncSetAttribute(flash_tf32,
                         cudaFuncAttributeMaxDynamicSharedMemorySize,
                         FLASH_SMEM_BYTES);

    // 1) QKV projection (tf32)
    {
        dim3 grid(THREE_DIM / 128, M_ROWS / 128);
        gemm_tf32<<<grid, 128>>>(x, w_qkv, qkv, M_ROWS, THREE_DIM, DIMc, nullptr);
    }
    // 2) RoPE + scatter
    rope_scatter<<<512, 256>>>(qkv, pos, q, k, v);
    // 3) Flash attention (tf32)
    {
        dim3 grid(Nn / 64, Bc * Hh);
        flash_tf32<<<grid, 128, FLASH_SMEM_BYTES>>>(q, k, v, attn);
    }
    // 4) Output projection + bias (tf32)
    {
        dim3 grid(DIMc / 128, M_ROWS / 128);
        gemm_tf32<<<grid, 128>>>(attn, w_out, out, M_ROWS, DIMc, DIMc, b_out);
    }
}